// round 5
// baseline (speedup 1.0000x reference)
#include <cuda_runtime.h>
#include <math.h>

// ---------------- problem constants ----------------
#define NTOK   8192      // B*H*W = 8*32*32
#define LSEQ   1024
#define D_IN   96
#define D_MID  192
#define DI     384
#define NST    16
#define RRANK  12
#define DBL_W  44        // R + 2N

// ---------------- scratch (device globals; no allocs allowed) ----------------
__device__ float g_xt [NTOK*D_IN];
__device__ float g_t1 [NTOK*D_IN];
__device__ float g_t2 [NTOK*D_MID];
__device__ float g_xz [NTOK*768];
__device__ float g_xc [NTOK*DI];
__device__ float g_dbl[NTOK*DBL_W];
__device__ float g_dt [NTOK*DI];
__device__ float g_y  [NTOK*DI];
__device__ float g_t3 [NTOK*D_MID];
__device__ float g_t4 [NTOK*D_MID];
__device__ float g_w1t[9*D_IN*D_IN];
__device__ float g_w4t[9*D_MID*D_MID];
__device__ float g_bns[768];
__device__ float g_bnb[768];
__device__ float g_A  [DI*NST];

// ---------------- activations ----------------
__device__ __forceinline__ float siluf(float x){ return x / (1.0f + __expf(-x)); }
__device__ __forceinline__ float geluf(float x){ return 0.5f*x*(1.0f + erff(x*0.70710678118654752f)); }
__device__ __forceinline__ float softplusf(float x){ return fmaxf(x,0.0f) + log1pf(__expf(-fabsf(x))); }

template<int ACT>
__device__ __forceinline__ float act_apply(float v){
  if (ACT==1) return geluf(v);
  if (ACT==2) return siluf(v);
  if (ACT==3) return softplusf(v);
  return v;
}

// ---------------- prep: BN affine params + A matrix ----------------
__global__ void prep_kernel(const float* __restrict__ g1,const float* __restrict__ b1,
                            const float* __restrict__ m1,const float* __restrict__ v1,
                            const float* __restrict__ g2,const float* __restrict__ b2,
                            const float* __restrict__ m2,const float* __restrict__ v2,
                            const float* __restrict__ g3,const float* __restrict__ b3,
                            const float* __restrict__ m3,const float* __restrict__ v3,
                            const float* __restrict__ g4,const float* __restrict__ b4,
                            const float* __restrict__ m4,const float* __restrict__ v4,
                            const float* __restrict__ A_log)
{
  int i = blockIdx.x*256 + threadIdx.x;
  const float eps = 1e-5f;
  if (i < 96){  float s = g1[i]*rsqrtf(v1[i]+eps); g_bns[i]     = s; g_bnb[i]     = b1[i]-m1[i]*s; }
  if (i < 192){ float s = g2[i]*rsqrtf(v2[i]+eps); g_bns[192+i] = s; g_bnb[192+i] = b2[i]-m2[i]*s;
                      s = g3[i]*rsqrtf(v3[i]+eps); g_bns[384+i] = s; g_bnb[384+i] = b3[i]-m3[i]*s;
                      s = g4[i]*rsqrtf(v4[i]+eps); g_bns[576+i] = s; g_bnb[576+i] = b4[i]-m4[i]*s; }
  if (i < DI*NST) g_A[i] = -expf(A_log[i]);
}

// ---------------- transpose NCHW -> token-major ----------------
__global__ void transpose_in(const float* __restrict__ x, float* __restrict__ out)
{
  __shared__ float tile[32][33];
  int bc = blockIdx.x, bl = blockIdx.y, b = blockIdx.z;
  int tx = threadIdx.x, ty = threadIdx.y;
  #pragma unroll
  for (int i = ty; i < 32; i += 8)
    tile[i][tx] = x[(b*D_IN + bc*32 + i)*LSEQ + bl*32 + tx];
  __syncthreads();
  #pragma unroll
  for (int i = ty; i < 32; i += 8)
    out[(b*LSEQ + bl*32 + i)*D_IN + bc*32 + tx] = tile[tx][i];
}

// ---------------- weight transform: (O,C,3,3) -> (tap,C,O) ----------------
__global__ void transform_w(const float* __restrict__ w, float* __restrict__ wt, int O, int Cin)
{
  int idx = blockIdx.x*256 + threadIdx.x;
  int total = O*Cin*9;
  if (idx < total){
    int o = idx/(Cin*9); int r = idx - o*(Cin*9); int c = r/9; int t = r - c*9;
    wt[(t*Cin + c)*O + o] = w[idx];
  }
}

// ---------------- tile config: high-occupancy 64x64 tiles ----------------
#define BM 64
#define BN 64
#define BK 32

// =====================================================================
// NT GEMM, BM=BN=64, BK=32, 256 threads, TM=TN=4, 4 CTAs/SM target.
// C[i,j] = act( dot(A[i,:K], B[j,:K]) * scale[j] + shift[j] )
// =====================================================================
template<int ACT>
__global__ void __launch_bounds__(256,4)
gemm_nt(const float* __restrict__ A, int lda,
        const float* __restrict__ B,
        float* __restrict__ C,
        int N, int K,
        const float* __restrict__ scale, const float* __restrict__ shift)
{
  __shared__ float As[BK][BM+4];
  __shared__ float Bs[BK][BN+4];
  const int tid  = threadIdx.x;
  const int row0 = blockIdx.x * BM;
  const int col0 = blockIdx.y * BN;
  const int tr = tid >> 4;        // 0..15
  const int tc = tid & 15;        // 0..15

  float acc[4][4];
  #pragma unroll
  for (int i=0;i<4;i++){ acc[i][0]=0.f; acc[i][1]=0.f; acc[i][2]=0.f; acc[i][3]=0.f; }

  const int ai = tid >> 2;        // 0..63 (A row)
  const int ak = (tid & 3) * 8;   // k base (8 floats per thread)
  const int bj = tid >> 2;        // 0..63 (B col)
  const int bk = (tid & 3) * 8;
  const bool jv = (col0 + bj) < N;

  for (int k0 = 0; k0 < K; k0 += BK){
    // --- A tile (64 x 32), k-major in smem ---
    const float* Arow = A + (size_t)(row0 + ai)*lda + k0 + ak;
    if (k0 + ak + 8 <= K){
      float4 v0 = *(const float4*)(Arow);
      float4 v1 = *(const float4*)(Arow + 4);
      As[ak+0][ai]=v0.x; As[ak+1][ai]=v0.y; As[ak+2][ai]=v0.z; As[ak+3][ai]=v0.w;
      As[ak+4][ai]=v1.x; As[ak+5][ai]=v1.y; As[ak+6][ai]=v1.z; As[ak+7][ai]=v1.w;
    } else {
      #pragma unroll
      for (int u=0;u<8;++u) As[ak+u][ai] = (k0+ak+u < K) ? Arow[u] : 0.f;
    }
    // --- B tile (64 x 32) ---
    const float* Brow = B + (size_t)(col0 + bj)*K + k0 + bk;
    if (jv && (k0 + bk + 8 <= K)){
      float4 v0 = *(const float4*)(Brow);
      float4 v1 = *(const float4*)(Brow + 4);
      Bs[bk+0][bj]=v0.x; Bs[bk+1][bj]=v0.y; Bs[bk+2][bj]=v0.z; Bs[bk+3][bj]=v0.w;
      Bs[bk+4][bj]=v1.x; Bs[bk+5][bj]=v1.y; Bs[bk+6][bj]=v1.z; Bs[bk+7][bj]=v1.w;
    } else {
      #pragma unroll
      for (int u=0;u<8;++u) Bs[bk+u][bj] = (jv && (k0+bk+u < K)) ? Brow[u] : 0.f;
    }
    __syncthreads();
    #pragma unroll
    for (int kk=0; kk<BK; ++kk){
      float4 a = *(const float4*)&As[kk][tr*4];
      float4 b = *(const float4*)&Bs[kk][tc*4];
      float av[4] = {a.x,a.y,a.z,a.w};
      float bv[4] = {b.x,b.y,b.z,b.w};
      #pragma unroll
      for (int i=0;i<4;i++)
        #pragma unroll
        for (int j=0;j<4;j++)
          acc[i][j] = fmaf(av[i], bv[j], acc[i][j]);
    }
    __syncthreads();
  }

  // epilogue (all Ns are multiples of 4)
  const int gcb = col0 + tc*4;
  if (gcb < N){
    float s[4], sh[4];
    #pragma unroll
    for (int j=0;j<4;j++){
      s[j]  = scale ? scale[gcb+j] : 1.f;
      sh[j] = shift ? shift[gcb+j] : 0.f;
    }
    #pragma unroll
    for (int i=0;i<4;i++){
      int gr = row0 + tr*4 + i;
      float4 o;
      o.x = act_apply<ACT>(acc[i][0]*s[0] + sh[0]);
      o.y = act_apply<ACT>(acc[i][1]*s[1] + sh[1]);
      o.z = act_apply<ACT>(acc[i][2]*s[2] + sh[2]);
      o.w = act_apply<ACT>(acc[i][3]*s[3] + sh[3]);
      *(float4*)&C[(size_t)gr*N + gcb] = o;
    }
  }
}

// =====================================================================
// 3x3 conv implicit GEMM (9 shifted taps), same 64x64x32 tiling.
// X token-major (NTOK, Cin); Wt (tap, Cin, Cout). Cin % 32 == 0.
// =====================================================================
template<int ACT, bool NCHW_OUT>
__global__ void __launch_bounds__(256,4)
conv3x3_gemm(const float* __restrict__ X,
             const float* __restrict__ Wt,
             float* __restrict__ C,
             int Cin, int N,
             const float* __restrict__ scale, const float* __restrict__ shift)
{
  __shared__ float As[BK][BM+4];
  __shared__ float Bs[BK][BN+4];
  const int tid  = threadIdx.x;
  const int row0 = blockIdx.x * BM;
  const int col0 = blockIdx.y * BN;
  const int tr = tid >> 4, tc = tid & 15;

  float acc[4][4];
  #pragma unroll
  for (int i=0;i<4;i++){ acc[i][0]=0.f; acc[i][1]=0.f; acc[i][2]=0.f; acc[i][3]=0.f; }

  const int ai = tid >> 2;
  const int ak = (tid & 3) * 8;

  // B loader: k = wk + u*16, j-group = wj0 (4 cols), coalesced along j
  const int wk  = tid >> 4;        // 0..15
  const int wj0 = (tid & 15) * 4;  // 0..60

  const int gt = row0 + ai;
  const int bb = gt >> 10;
  const int ll = gt & 1023;
  const int hh = ll >> 5, ww = ll & 31;

  for (int tap = 0; tap < 9; ++tap){
    const int dy = tap/3 - 1, dx = tap - (tap/3)*3 - 1;
    const int nh = hh + dy, nw = ww + dx;
    const bool valid = ((unsigned)nh < 32u) && ((unsigned)nw < 32u);
    const float* src = X + (size_t)((bb<<10) + (nh<<5) + nw) * Cin;
    for (int c0 = 0; c0 < Cin; c0 += BK){
      // A
      float4 v0 = make_float4(0.f,0.f,0.f,0.f), v1 = v0;
      if (valid){
        v0 = *(const float4*)(src + c0 + ak);
        v1 = *(const float4*)(src + c0 + ak + 4);
      }
      As[ak+0][ai]=v0.x; As[ak+1][ai]=v0.y; As[ak+2][ai]=v0.z; As[ak+3][ai]=v0.w;
      As[ak+4][ai]=v1.x; As[ak+5][ai]=v1.y; As[ak+6][ai]=v1.z; As[ak+7][ai]=v1.w;
      // B (weights): 2 passes over k (wk, wk+16)
      #pragma unroll
      for (int u=0; u<2; ++u){
        int k = wk + u*16;
        const float* wr = Wt + (size_t)(tap*Cin + c0 + k)*N + col0 + wj0;
        if (col0 + wj0 + 3 < N){
          float4 v = *(const float4*)(wr);
          Bs[k][wj0+0]=v.x; Bs[k][wj0+1]=v.y; Bs[k][wj0+2]=v.z; Bs[k][wj0+3]=v.w;
        } else {
          #pragma unroll
          for (int q=0;q<4;++q) Bs[k][wj0+q] = (col0+wj0+q < N) ? wr[q] : 0.f;
        }
      }
      __syncthreads();
      #pragma unroll
      for (int kk=0; kk<BK; ++kk){
        float4 a = *(const float4*)&As[kk][tr*4];
        float4 b = *(const float4*)&Bs[kk][tc*4];
        float av[4] = {a.x,a.y,a.z,a.w};
        float bv[4] = {b.x,b.y,b.z,b.w};
        #pragma unroll
        for (int i=0;i<4;i++)
          #pragma unroll
          for (int j=0;j<4;j++)
            acc[i][j] = fmaf(av[i], bv[j], acc[i][j]);
      }
      __syncthreads();
    }
  }

  const int gcb = col0 + tc*4;
  if (gcb < N){
    float s[4], sh[4];
    #pragma unroll
    for (int j=0;j<4;j++){
      s[j]  = scale ? scale[gcb+j] : 1.f;
      sh[j] = shift ? shift[gcb+j] : 0.f;
    }
    #pragma unroll
    for (int i=0;i<4;i++){
      int gr = row0 + tr*4 + i;
      float r0 = act_apply<ACT>(acc[i][0]*s[0] + sh[0]);
      float r1 = act_apply<ACT>(acc[i][1]*s[1] + sh[1]);
      float r2 = act_apply<ACT>(acc[i][2]*s[2] + sh[2]);
      float r3 = act_apply<ACT>(acc[i][3]*s[3] + sh[3]);
      if (NCHW_OUT){
        int ob = gr >> 10, ol = gr & 1023;
        C[(size_t)(ob*N + gcb+0)*LSEQ + ol] = r0;
        C[(size_t)(ob*N + gcb+1)*LSEQ + ol] = r1;
        C[(size_t)(ob*N + gcb+2)*LSEQ + ol] = r2;
        C[(size_t)(ob*N + gcb+3)*LSEQ + ol] = r3;
      } else {
        *(float4*)&C[(size_t)gr*N + gcb] = make_float4(r0,r1,r2,r3);
      }
    }
  }
}

// ---------------- causal depthwise conv (K=4) + SiLU ----------------
__global__ void dwconv_silu(const float* __restrict__ cw, const float* __restrict__ cb)
{
  int idx = blockIdx.x*256 + threadIdx.x;
  if (idx >= NTOK*DI) return;
  int d = idx % DI;
  int tok = idx / DI;
  int b = tok >> 10, l = tok & 1023;
  float acc = cb[d];
  const float* xi = g_xz + (size_t)(b<<10)*768 + d;
  #pragma unroll
  for (int k=0;k<4;++k){
    int ll = l + k - 3;
    if (ll >= 0) acc = fmaf(xi[(size_t)ll*768], cw[d*4+k], acc);
  }
  g_xc[idx] = siluf(acc);
}

// ---------------- selective scan ----------------
__global__ void __launch_bounds__(128)
scan_kernel(const float* __restrict__ Dp)
{
  int gid = (blockIdx.x * 128 + threadIdx.x) >> 4;
  int n   = threadIdx.x & 15;
  int b   = gid / DI;
  int d   = gid - b*DI;
  float Aval = g_A[d*NST + n];
  float dpv  = Dp[d];
  float h = 0.f;
  const float* __restrict__ dtp = g_dt  + (size_t)(b<<10)*DI + d;
  const float* __restrict__ xcp = g_xc  + (size_t)(b<<10)*DI + d;
  const float* __restrict__ zp  = g_xz  + (size_t)(b<<10)*768 + 384 + d;
  const float* __restrict__ blp = g_dbl + (size_t)(b<<10)*DBL_W;
  float* __restrict__ yp = g_y + (size_t)(b<<10)*DI + d;

  #pragma unroll 4
  for (int l = 0; l < LSEQ; ++l){
    float dtv = dtp[(size_t)l*DI];
    float xcv = xcp[(size_t)l*DI];
    float Bv  = blp[(size_t)l*DBL_W + RRANK + n];
    float Cv  = blp[(size_t)l*DBL_W + RRANK + NST + n];
    float dA  = __expf(dtv * Aval);
    h = fmaf(dA, h, dtv*Bv*xcv);
    float p = h * Cv;
    p += __shfl_xor_sync(0xffffffffu, p, 8, 16);
    p += __shfl_xor_sync(0xffffffffu, p, 4, 16);
    p += __shfl_xor_sync(0xffffffffu, p, 2, 16);
    p += __shfl_xor_sync(0xffffffffu, p, 1, 16);
    if (n == 0){
      float zv = zp[(size_t)l*768];
      yp[(size_t)l*DI] = (p + xcv*dpv) * siluf(zv);
    }
  }
}

// ---------------- host launcher ----------------
extern "C" void kernel_launch(void* const* d_in, const int* in_sizes, int n_in,
                              void* d_out, int out_size)
{
  (void)in_sizes; (void)n_in; (void)out_size;
  const float* x    = (const float*)d_in[0];
  const float* w1   = (const float*)d_in[1];
  const float* g1   = (const float*)d_in[2];
  const float* b1   = (const float*)d_in[3];
  const float* m1   = (const float*)d_in[4];
  const float* v1   = (const float*)d_in[5];
  const float* w2   = (const float*)d_in[6];
  const float* g2   = (const float*)d_in[7];
  const float* b2   = (const float*)d_in[8];
  const float* m2   = (const float*)d_in[9];
  const float* v2   = (const float*)d_in[10];
  const float* in_w = (const float*)d_in[11];
  const float* cw   = (const float*)d_in[12];
  const float* cb   = (const float*)d_in[13];
  const float* xp_w = (const float*)d_in[14];
  const float* dt_w = (const float*)d_in[15];
  const float* dt_b = (const float*)d_in[16];
  const float* A_log= (const float*)d_in[17];
  const float* Dp   = (const float*)d_in[18];
  const float* out_w= (const float*)d_in[19];
  const float* w3   = (const float*)d_in[20];
  const float* g3   = (const float*)d_in[21];
  const float* b3   = (const float*)d_in[22];
  const float* m3   = (const float*)d_in[23];
  const float* v3   = (const float*)d_in[24];
  const float* w4   = (const float*)d_in[25];
  const float* g4   = (const float*)d_in[26];
  const float* b4   = (const float*)d_in[27];
  const float* m4   = (const float*)d_in[28];
  const float* v4   = (const float*)d_in[29];

  float *p_xt,*p_t1,*p_t2,*p_xz,*p_xc,*p_dbl,*p_dt,*p_y,*p_t3,*p_t4,*p_w1t,*p_w4t,*p_bns,*p_bnb;
  cudaGetSymbolAddress((void**)&p_xt , g_xt );
  cudaGetSymbolAddress((void**)&p_t1 , g_t1 );
  cudaGetSymbolAddress((void**)&p_t2 , g_t2 );
  cudaGetSymbolAddress((void**)&p_xz , g_xz );
  cudaGetSymbolAddress((void**)&p_xc , g_xc );
  cudaGetSymbolAddress((void**)&p_dbl, g_dbl);
  cudaGetSymbolAddress((void**)&p_dt , g_dt );
  cudaGetSymbolAddress((void**)&p_y  , g_y  );
  cudaGetSymbolAddress((void**)&p_t3 , g_t3 );
  cudaGetSymbolAddress((void**)&p_t4 , g_t4 );
  cudaGetSymbolAddress((void**)&p_w1t, g_w1t);
  cudaGetSymbolAddress((void**)&p_w4t, g_w4t);
  cudaGetSymbolAddress((void**)&p_bns, g_bns);
  cudaGetSymbolAddress((void**)&p_bnb, g_bnb);

  // Launch order keeps conv1 at my 0-based launch #3 (the ncu-captured slot).
  prep_kernel<<<24,256>>>(g1,b1,m1,v1, g2,b2,m2,v2, g3,b3,m3,v3, g4,b4,m4,v4, A_log);  // #0
  transpose_in<<<dim3(3,32,8), dim3(32,8)>>>(x, p_xt);                                  // #1
  transform_w<<<(D_IN*D_IN*9+255)/256,256>>>(w1, p_w1t, D_IN, D_IN);                    // #2
  // conv1 3x3 + BN1 + GELU  (PROFILED SLOT) — grid 128x2 = 256 CTAs
  conv3x3_gemm<1,false><<<dim3(NTOK/BM, 2),256>>>(p_xt, p_w1t, p_t1, D_IN, D_IN, p_bns+0, p_bnb+0); // #3
  transform_w<<<(D_MID*D_MID*9+255)/256,256>>>(w4, p_w4t, D_MID, D_MID);                // #4
  // conv2 1x1 + BN2 + SiLU (128x3)
  gemm_nt<2><<<dim3(NTOK/BM, 3),256>>>(p_t1, D_IN, w2, p_t2, D_MID, D_IN, p_bns+192, p_bnb+192);
  // in_proj (128x12)
  gemm_nt<0><<<dim3(NTOK/BM, 12),256>>>(p_t2, D_MID, in_w, p_xz, 768, D_MID, nullptr, nullptr);
  dwconv_silu<<<(NTOK*DI)/256,256>>>(cw, cb);
  // x_proj (128x1)
  gemm_nt<0><<<dim3(NTOK/BM, 1),256>>>(p_xc, DI, xp_w, p_dbl, DBL_W, DI, nullptr, nullptr);
  // dt_proj + softplus (128x6)
  gemm_nt<3><<<dim3(NTOK/BM, 6),256>>>(p_dbl, DBL_W, dt_w, p_dt, DI, RRANK, nullptr, dt_b);
  scan_kernel<<<(NTOK/LSEQ)*DI*16/128,128>>>(Dp);
  // out_proj (128x3)
  gemm_nt<0><<<dim3(NTOK/BM, 3),256>>>(p_y, DI, out_w, p_t3, D_MID, DI, nullptr, nullptr);
  // conv3 1x1 + BN3 + SiLU (128x3)
  gemm_nt<2><<<dim3(NTOK/BM, 3),256>>>(p_t3, D_MID, w3, p_t4, D_MID, D_MID, p_bns+384, p_bnb+384);
  // conv4 3x3 + BN4 + GELU -> NCHW (128x3)
  conv3x3_gemm<1,true><<<dim3(NTOK/BM, 3),256>>>(p_t4, p_w4t, (float*)d_out, D_MID, D_MID, p_bns+576, p_bnb+576);
}

// round 6
// speedup vs baseline: 1.4601x; 1.4601x over previous
#include <cuda_runtime.h>
#include <math.h>

// ---------------- problem constants ----------------
#define NTOK   8192      // B*H*W = 8*32*32
#define LSEQ   1024
#define D_IN   96
#define D_MID  192
#define DI     384
#define NST    16
#define RRANK  12
#define DBL_W  44        // R + 2N

// ---------------- scratch (device globals; no allocs allowed) ----------------
__device__ float g_xt [NTOK*D_IN];
__device__ float g_t1 [NTOK*D_IN];
__device__ float g_t2 [NTOK*D_MID];
__device__ float g_xz [NTOK*768];
__device__ float g_xc [NTOK*DI];
__device__ float g_dbl[NTOK*DBL_W];
__device__ float g_dt [NTOK*DI];
__device__ float g_y  [NTOK*DI];
__device__ float g_t3 [NTOK*D_MID];
__device__ float g_t4 [NTOK*D_MID];
__device__ float g_w1t[9*D_IN*D_IN];
__device__ float g_w4t[9*D_MID*D_MID];
__device__ float g_bns[768];
__device__ float g_bnb[768];
__device__ float g_A  [DI*NST];

// ---------------- activations ----------------
__device__ __forceinline__ float siluf(float x){ return x / (1.0f + __expf(-x)); }
__device__ __forceinline__ float geluf(float x){ return 0.5f*x*(1.0f + erff(x*0.70710678118654752f)); }
__device__ __forceinline__ float softplusf(float x){ return fmaxf(x,0.0f) + log1pf(__expf(-fabsf(x))); }

template<int ACT>
__device__ __forceinline__ float act_apply(float v){
  if (ACT==1) return geluf(v);
  if (ACT==2) return siluf(v);
  if (ACT==3) return softplusf(v);
  return v;
}

// ---------------- prep: BN affine params + A matrix ----------------
__global__ void prep_kernel(const float* __restrict__ g1,const float* __restrict__ b1,
                            const float* __restrict__ m1,const float* __restrict__ v1,
                            const float* __restrict__ g2,const float* __restrict__ b2,
                            const float* __restrict__ m2,const float* __restrict__ v2,
                            const float* __restrict__ g3,const float* __restrict__ b3,
                            const float* __restrict__ m3,const float* __restrict__ v3,
                            const float* __restrict__ g4,const float* __restrict__ b4,
                            const float* __restrict__ m4,const float* __restrict__ v4,
                            const float* __restrict__ A_log)
{
  int i = blockIdx.x*256 + threadIdx.x;
  const float eps = 1e-5f;
  if (i < 96){  float s = g1[i]*rsqrtf(v1[i]+eps); g_bns[i]     = s; g_bnb[i]     = b1[i]-m1[i]*s; }
  if (i < 192){ float s = g2[i]*rsqrtf(v2[i]+eps); g_bns[192+i] = s; g_bnb[192+i] = b2[i]-m2[i]*s;
                      s = g3[i]*rsqrtf(v3[i]+eps); g_bns[384+i] = s; g_bnb[384+i] = b3[i]-m3[i]*s;
                      s = g4[i]*rsqrtf(v4[i]+eps); g_bns[576+i] = s; g_bnb[576+i] = b4[i]-m4[i]*s; }
  if (i < DI*NST) g_A[i] = -expf(A_log[i]);
}

// ---------------- transpose NCHW -> token-major ----------------
__global__ void transpose_in(const float* __restrict__ x, float* __restrict__ out)
{
  __shared__ float tile[32][33];
  int bc = blockIdx.x, bl = blockIdx.y, b = blockIdx.z;
  int tx = threadIdx.x, ty = threadIdx.y;
  #pragma unroll
  for (int i = ty; i < 32; i += 8)
    tile[i][tx] = x[(b*D_IN + bc*32 + i)*LSEQ + bl*32 + tx];
  __syncthreads();
  #pragma unroll
  for (int i = ty; i < 32; i += 8)
    out[(b*LSEQ + bl*32 + i)*D_IN + bc*32 + tx] = tile[tx][i];
}

// ---------------- weight transform: (O,C,3,3) -> (tap,C,O) ----------------
__global__ void transform_w(const float* __restrict__ w, float* __restrict__ wt, int O, int Cin)
{
  int idx = blockIdx.x*256 + threadIdx.x;
  int total = O*Cin*9;
  if (idx < total){
    int o = idx/(Cin*9); int r = idx - o*(Cin*9); int c = r/9; int t = r - c*9;
    wt[(t*Cin + c)*O + o] = w[idx];
  }
}

// ---------------- tile config: BM=64, 128 threads, TM=8 x TN=4 ----------------
#define BM 64
#define BN 64
#define BK 16

// =====================================================================
// NT GEMM: 128 threads, BM=64, BN=64, TM=8, TN=4.
// Same register tile as the proven R4 config; half-size CTA so grids
// double and 2-5 CTAs/SM overlap each other's barriers/latency.
// =====================================================================
template<int ACT>
__global__ void __launch_bounds__(128)
gemm_nt(const float* __restrict__ A, int lda,
        const float* __restrict__ B,
        float* __restrict__ C,
        int N, int K,
        const float* __restrict__ scale, const float* __restrict__ shift)
{
  __shared__ float As[BK][BM];
  __shared__ float Bs[BK][BN+4];
  const int tid  = threadIdx.x;
  const int row0 = blockIdx.x * BM;
  const int col0 = blockIdx.y * BN;
  const int tr = tid >> 4;        // 0..7  (8 rows of 8)
  const int tc = tid & 15;        // 0..15 (16 cols of 4)

  float acc[8][4];
  #pragma unroll
  for (int i=0;i<8;i++){ acc[i][0]=0.f; acc[i][1]=0.f; acc[i][2]=0.f; acc[i][3]=0.f; }

  const int ai = tid >> 1;        // 0..63
  const int ak = (tid & 1) * 8;
  const int bj = tid >> 1;        // 0..63
  const int bk = (tid & 1) * 8;
  const bool jv = (col0 + bj) < N;

  for (int k0 = 0; k0 < K; k0 += BK){
    // --- A tile (64 x 16) ---
    const float* Arow = A + (size_t)(row0 + ai)*lda + k0 + ak;
    if (k0 + ak + 8 <= K){
      float4 v0 = *(const float4*)(Arow);
      float4 v1 = *(const float4*)(Arow + 4);
      As[ak+0][ai]=v0.x; As[ak+1][ai]=v0.y; As[ak+2][ai]=v0.z; As[ak+3][ai]=v0.w;
      As[ak+4][ai]=v1.x; As[ak+5][ai]=v1.y; As[ak+6][ai]=v1.z; As[ak+7][ai]=v1.w;
    } else {
      #pragma unroll
      for (int u=0;u<8;++u) As[ak+u][ai] = (k0+ak+u < K) ? Arow[u] : 0.f;
    }
    // --- B tile (64 x 16) ---
    const float* Brow = B + (size_t)(col0 + bj)*K + k0 + bk;
    if (jv && (k0 + bk + 8 <= K)){
      float4 v0 = *(const float4*)(Brow);
      float4 v1 = *(const float4*)(Brow + 4);
      Bs[bk+0][bj]=v0.x; Bs[bk+1][bj]=v0.y; Bs[bk+2][bj]=v0.z; Bs[bk+3][bj]=v0.w;
      Bs[bk+4][bj]=v1.x; Bs[bk+5][bj]=v1.y; Bs[bk+6][bj]=v1.z; Bs[bk+7][bj]=v1.w;
    } else {
      #pragma unroll
      for (int u=0;u<8;++u) Bs[bk+u][bj] = (jv && (k0+bk+u < K)) ? Brow[u] : 0.f;
    }
    __syncthreads();
    #pragma unroll
    for (int kk=0; kk<BK; ++kk){
      float4 a0 = *(const float4*)&As[kk][tr*8];
      float4 a1 = *(const float4*)&As[kk][tr*8+4];
      float4 b  = *(const float4*)&Bs[kk][tc*4];
      float av[8] = {a0.x,a0.y,a0.z,a0.w,a1.x,a1.y,a1.z,a1.w};
      float bv[4] = {b.x,b.y,b.z,b.w};
      #pragma unroll
      for (int i=0;i<8;i++)
        #pragma unroll
        for (int j=0;j<4;j++)
          acc[i][j] = fmaf(av[i], bv[j], acc[i][j]);
    }
    __syncthreads();
  }

  const int gcb = col0 + tc*4;
  if (gcb < N){
    float s[4], sh[4];
    #pragma unroll
    for (int j=0;j<4;j++){
      s[j]  = scale ? scale[gcb+j] : 1.f;
      sh[j] = shift ? shift[gcb+j] : 0.f;
    }
    #pragma unroll
    for (int i=0;i<8;i++){
      int gr = row0 + tr*8 + i;
      float4 o;
      o.x = act_apply<ACT>(acc[i][0]*s[0] + sh[0]);
      o.y = act_apply<ACT>(acc[i][1]*s[1] + sh[1]);
      o.z = act_apply<ACT>(acc[i][2]*s[2] + sh[2]);
      o.w = act_apply<ACT>(acc[i][3]*s[3] + sh[3]);
      *(float4*)&C[(size_t)gr*N + gcb] = o;
    }
  }
}

// =====================================================================
// 3x3 conv implicit GEMM (9 shifted taps), BM=64 / 128-thread version.
// X token-major (NTOK, Cin); Wt (tap, Cin, Cout). Cin % 16 == 0.
// =====================================================================
template<int ACT, bool NCHW_OUT>
__global__ void __launch_bounds__(128)
conv3x3_gemm(const float* __restrict__ X,
             const float* __restrict__ Wt,
             float* __restrict__ C,
             int Cin, int N,
             const float* __restrict__ scale, const float* __restrict__ shift)
{
  __shared__ float As[BK][BM];
  __shared__ float Bs[BK][BN+4];
  const int tid  = threadIdx.x;
  const int row0 = blockIdx.x * BM;
  const int col0 = blockIdx.y * BN;
  const int tr = tid >> 4, tc = tid & 15;

  float acc[8][4];
  #pragma unroll
  for (int i=0;i<8;i++){ acc[i][0]=0.f; acc[i][1]=0.f; acc[i][2]=0.f; acc[i][3]=0.f; }

  const int ai  = tid >> 1;       // 0..63
  const int ak  = (tid & 1) * 8;
  const int bj  = tid & 63;       // 0..63 (coalesced along j)
  const int bq  = tid >> 6;       // 0..1  (k half)
  const bool jv = (col0 + bj) < N;

  const int gt = row0 + ai;
  const int bb = gt >> 10;
  const int ll = gt & 1023;
  const int hh = ll >> 5, ww = ll & 31;

  for (int tap = 0; tap < 9; ++tap){
    const int dy = tap/3 - 1, dx = tap - (tap/3)*3 - 1;
    const int nh = hh + dy, nw = ww + dx;
    const bool valid = ((unsigned)nh < 32u) && ((unsigned)nw < 32u);
    const float* src = X + (size_t)((bb<<10) + (nh<<5) + nw) * Cin;
    for (int c0 = 0; c0 < Cin; c0 += BK){
      float4 v0 = make_float4(0.f,0.f,0.f,0.f), v1 = v0;
      if (valid){
        v0 = *(const float4*)(src + c0 + ak);
        v1 = *(const float4*)(src + c0 + ak + 4);
      }
      As[ak+0][ai]=v0.x; As[ak+1][ai]=v0.y; As[ak+2][ai]=v0.z; As[ak+3][ai]=v0.w;
      As[ak+4][ai]=v1.x; As[ak+5][ai]=v1.y; As[ak+6][ai]=v1.z; As[ak+7][ai]=v1.w;

      const float* wrow = Wt + (size_t)(tap*Cin + c0 + bq*8)*N + col0 + bj;
      #pragma unroll
      for (int u=0; u<8; ++u){
        Bs[bq*8 + u][bj] = jv ? wrow[(size_t)u*N] : 0.f;
      }
      __syncthreads();
      #pragma unroll
      for (int kk=0; kk<BK; ++kk){
        float4 a0 = *(const float4*)&As[kk][tr*8];
        float4 a1 = *(const float4*)&As[kk][tr*8+4];
        float4 b  = *(const float4*)&Bs[kk][tc*4];
        float av[8] = {a0.x,a0.y,a0.z,a0.w,a1.x,a1.y,a1.z,a1.w};
        float bv[4] = {b.x,b.y,b.z,b.w};
        #pragma unroll
        for (int i=0;i<8;i++)
          #pragma unroll
          for (int j=0;j<4;j++)
            acc[i][j] = fmaf(av[i], bv[j], acc[i][j]);
      }
      __syncthreads();
    }
  }

  const int gcb = col0 + tc*4;
  if (gcb < N){
    float s[4], sh[4];
    #pragma unroll
    for (int j=0;j<4;j++){
      s[j]  = scale ? scale[gcb+j] : 1.f;
      sh[j] = shift ? shift[gcb+j] : 0.f;
    }
    #pragma unroll
    for (int i=0;i<8;i++){
      int gr = row0 + tr*8 + i;
      float r0 = act_apply<ACT>(acc[i][0]*s[0] + sh[0]);
      float r1 = act_apply<ACT>(acc[i][1]*s[1] + sh[1]);
      float r2 = act_apply<ACT>(acc[i][2]*s[2] + sh[2]);
      float r3 = act_apply<ACT>(acc[i][3]*s[3] + sh[3]);
      if (NCHW_OUT){
        int ob = gr >> 10, ol = gr & 1023;
        C[(size_t)(ob*N + gcb+0)*LSEQ + ol] = r0;
        C[(size_t)(ob*N + gcb+1)*LSEQ + ol] = r1;
        C[(size_t)(ob*N + gcb+2)*LSEQ + ol] = r2;
        C[(size_t)(ob*N + gcb+3)*LSEQ + ol] = r3;
      } else {
        *(float4*)&C[(size_t)gr*N + gcb] = make_float4(r0,r1,r2,r3);
      }
    }
  }
}

// ---------------- causal depthwise conv (K=4) + SiLU ----------------
__global__ void dwconv_silu(const float* __restrict__ cw, const float* __restrict__ cb)
{
  int idx = blockIdx.x*256 + threadIdx.x;
  if (idx >= NTOK*DI) return;
  int d = idx % DI;
  int tok = idx / DI;
  int b = tok >> 10, l = tok & 1023;
  float acc = cb[d];
  const float* xi = g_xz + (size_t)(b<<10)*768 + d;
  #pragma unroll
  for (int k=0;k<4;++k){
    int ll = l + k - 3;
    if (ll >= 0) acc = fmaf(xi[(size_t)ll*768], cw[d*4+k], acc);
  }
  g_xc[idx] = siluf(acc);
}

// ---------------- selective scan ----------------
__global__ void __launch_bounds__(128)
scan_kernel(const float* __restrict__ Dp)
{
  int gid = (blockIdx.x * 128 + threadIdx.x) >> 4;
  int n   = threadIdx.x & 15;
  int b   = gid / DI;
  int d   = gid - b*DI;
  float Aval = g_A[d*NST + n];
  float dpv  = Dp[d];
  float h = 0.f;
  const float* __restrict__ dtp = g_dt  + (size_t)(b<<10)*DI + d;
  const float* __restrict__ xcp = g_xc  + (size_t)(b<<10)*DI + d;
  const float* __restrict__ zp  = g_xz  + (size_t)(b<<10)*768 + 384 + d;
  const float* __restrict__ blp = g_dbl + (size_t)(b<<10)*DBL_W;
  float* __restrict__ yp = g_y + (size_t)(b<<10)*DI + d;

  #pragma unroll 4
  for (int l = 0; l < LSEQ; ++l){
    float dtv = dtp[(size_t)l*DI];
    float xcv = xcp[(size_t)l*DI];
    float Bv  = blp[(size_t)l*DBL_W + RRANK + n];
    float Cv  = blp[(size_t)l*DBL_W + RRANK + NST + n];
    float dA  = __expf(dtv * Aval);
    h = fmaf(dA, h, dtv*Bv*xcv);
    float p = h * Cv;
    p += __shfl_xor_sync(0xffffffffu, p, 8, 16);
    p += __shfl_xor_sync(0xffffffffu, p, 4, 16);
    p += __shfl_xor_sync(0xffffffffu, p, 2, 16);
    p += __shfl_xor_sync(0xffffffffu, p, 1, 16);
    if (n == 0){
      float zv = zp[(size_t)l*768];
      yp[(size_t)l*DI] = (p + xcv*dpv) * siluf(zv);
    }
  }
}

// ---------------- host launcher ----------------
extern "C" void kernel_launch(void* const* d_in, const int* in_sizes, int n_in,
                              void* d_out, int out_size)
{
  (void)in_sizes; (void)n_in; (void)out_size;
  const float* x    = (const float*)d_in[0];
  const float* w1   = (const float*)d_in[1];
  const float* g1   = (const float*)d_in[2];
  const float* b1   = (const float*)d_in[3];
  const float* m1   = (const float*)d_in[4];
  const float* v1   = (const float*)d_in[5];
  const float* w2   = (const float*)d_in[6];
  const float* g2   = (const float*)d_in[7];
  const float* b2   = (const float*)d_in[8];
  const float* m2   = (const float*)d_in[9];
  const float* v2   = (const float*)d_in[10];
  const float* in_w = (const float*)d_in[11];
  const float* cw   = (const float*)d_in[12];
  const float* cb   = (const float*)d_in[13];
  const float* xp_w = (const float*)d_in[14];
  const float* dt_w = (const float*)d_in[15];
  const float* dt_b = (const float*)d_in[16];
  const float* A_log= (const float*)d_in[17];
  const float* Dp   = (const float*)d_in[18];
  const float* out_w= (const float*)d_in[19];
  const float* w3   = (const float*)d_in[20];
  const float* g3   = (const float*)d_in[21];
  const float* b3   = (const float*)d_in[22];
  const float* m3   = (const float*)d_in[23];
  const float* v3   = (const float*)d_in[24];
  const float* w4   = (const float*)d_in[25];
  const float* g4   = (const float*)d_in[26];
  const float* b4   = (const float*)d_in[27];
  const float* m4   = (const float*)d_in[28];
  const float* v4   = (const float*)d_in[29];

  float *p_xt,*p_t1,*p_t2,*p_xz,*p_xc,*p_dbl,*p_dt,*p_y,*p_t3,*p_t4,*p_w1t,*p_w4t,*p_bns,*p_bnb;
  cudaGetSymbolAddress((void**)&p_xt , g_xt );
  cudaGetSymbolAddress((void**)&p_t1 , g_t1 );
  cudaGetSymbolAddress((void**)&p_t2 , g_t2 );
  cudaGetSymbolAddress((void**)&p_xz , g_xz );
  cudaGetSymbolAddress((void**)&p_xc , g_xc );
  cudaGetSymbolAddress((void**)&p_dbl, g_dbl);
  cudaGetSymbolAddress((void**)&p_dt , g_dt );
  cudaGetSymbolAddress((void**)&p_y  , g_y  );
  cudaGetSymbolAddress((void**)&p_t3 , g_t3 );
  cudaGetSymbolAddress((void**)&p_t4 , g_t4 );
  cudaGetSymbolAddress((void**)&p_w1t, g_w1t);
  cudaGetSymbolAddress((void**)&p_w4t, g_w4t);
  cudaGetSymbolAddress((void**)&p_bns, g_bns);
  cudaGetSymbolAddress((void**)&p_bnb, g_bnb);

  // Launch order keeps conv1 at my 0-based launch #3 (the ncu-captured slot).
  prep_kernel<<<24,256>>>(g1,b1,m1,v1, g2,b2,m2,v2, g3,b3,m3,v3, g4,b4,m4,v4, A_log);  // #0
  transpose_in<<<dim3(3,32,8), dim3(32,8)>>>(x, p_xt);                                  // #1
  transform_w<<<(D_IN*D_IN*9+255)/256,256>>>(w1, p_w1t, D_IN, D_IN);                    // #2
  // conv1 3x3 + BN1 + GELU  (PROFILED SLOT) — grid 128x2 = 256 CTAs
  conv3x3_gemm<1,false><<<dim3(NTOK/BM, 2),128>>>(p_xt, p_w1t, p_t1, D_IN, D_IN, p_bns+0, p_bnb+0); // #3
  transform_w<<<(D_MID*D_MID*9+255)/256,256>>>(w4, p_w4t, D_MID, D_MID);                // #4
  // conv2 1x1 + BN2 + SiLU (128x3 = 384 CTAs)
  gemm_nt<2><<<dim3(NTOK/BM, 3),128>>>(p_t1, D_IN, w2, p_t2, D_MID, D_IN, p_bns+192, p_bnb+192);
  // in_proj (128x12 = 1536 CTAs)
  gemm_nt<0><<<dim3(NTOK/BM, 12),128>>>(p_t2, D_MID, in_w, p_xz, 768, D_MID, nullptr, nullptr);
  dwconv_silu<<<(NTOK*DI)/256,256>>>(cw, cb);
  // x_proj (128x1 = 128... small K-output; fine)
  gemm_nt<0><<<dim3(NTOK/BM, 1),128>>>(p_xc, DI, xp_w, p_dbl, DBL_W, DI, nullptr, nullptr);
  // dt_proj + softplus (128x6 = 768 CTAs)
  gemm_nt<3><<<dim3(NTOK/BM, 6),128>>>(p_dbl, DBL_W, dt_w, p_dt, DI, RRANK, nullptr, dt_b);
  scan_kernel<<<(NTOK/LSEQ)*DI*16/128,128>>>(Dp);
  // out_proj (128x3 = 384 CTAs)
  gemm_nt<0><<<dim3(NTOK/BM, 3),128>>>(p_y, DI, out_w, p_t3, D_MID, DI, nullptr, nullptr);
  // conv3 1x1 + BN3 + SiLU (384 CTAs)
  gemm_nt<2><<<dim3(NTOK/BM, 3),128>>>(p_t3, D_MID, w3, p_t4, D_MID, D_MID, p_bns+384, p_bnb+384);
  // conv4 3x3 + BN4 + GELU -> NCHW (384 CTAs)
  conv3x3_gemm<1,true><<<dim3(NTOK/BM, 3),128>>>(p_t4, p_w4t, (float*)d_out, D_MID, D_MID, p_bns+576, p_bnb+576);
}